// round 1
// baseline (speedup 1.0000x reference)
#include <cuda_runtime.h>

// Problem constants
#define BB 8
#define SS 1024
#define EE 256
#define HH 8
#define DD 32
static constexpr float NORM_F = 0.17677669529663687f;  // 1/sqrt(32)

// Scratch (allocation-free): 5 x [B,S,E] fp32 = 40 MB
__device__ float g_Qh[BB * SS * EE];
__device__ float g_Kh[BB * SS * EE];
__device__ float g_Vh[BB * SS * EE];
__device__ float g_G [BB * SS * EE];
__device__ float g_O [BB * SS * EE];

// ---------------------------------------------------------------------------
// SGEMM: C[M,256] = scale * (A[M,256] @ W[256,256]^T) + bias[256]?
// Optional gate: A_eff = A * sigmoid(gate) elementwise (fuses the output gating)
// Tile 128x64x16, 256 threads, 8x4 per-thread microtile.
// ---------------------------------------------------------------------------
__global__ __launch_bounds__(256) void sgemm_kernel(
    const float* __restrict__ A, const float* __restrict__ W,
    const float* __restrict__ bias, const float* __restrict__ gate,
    float* __restrict__ C, float scale)
{
    constexpr int BM = 128, BN = 64, BK = 16;
    __shared__ float As[BK][BM];   // A^T tile
    __shared__ float Bs[BK][BN];   // W^T tile (Bs[k][n] = W[n][k])

    const int tid = threadIdx.x;
    const int tx = tid % 16;       // n direction (x4)
    const int ty = tid / 16;       // m direction (x8)
    const int m0 = blockIdx.y * BM;
    const int n0 = blockIdx.x * BN;

    float acc[8][4];
#pragma unroll
    for (int i = 0; i < 8; i++)
#pragma unroll
        for (int j = 0; j < 4; j++) acc[i][j] = 0.f;

    for (int k0 = 0; k0 < EE; k0 += BK) {
        // Load A tile: 128 rows x 16 cols = 512 float4, 2 per thread
#pragma unroll
        for (int i = 0; i < 2; i++) {
            int idx = tid + 256 * i;          // 0..511
            int row = idx >> 2, c4 = idx & 3;
            size_t goff = (size_t)(m0 + row) * EE + k0 + c4 * 4;
            float4 a = *reinterpret_cast<const float4*>(&A[goff]);
            if (gate) {
                float4 g = *reinterpret_cast<const float4*>(&gate[goff]);
                a.x *= 1.f / (1.f + __expf(-g.x));
                a.y *= 1.f / (1.f + __expf(-g.y));
                a.z *= 1.f / (1.f + __expf(-g.z));
                a.w *= 1.f / (1.f + __expf(-g.w));
            }
            As[c4 * 4 + 0][row] = a.x;
            As[c4 * 4 + 1][row] = a.y;
            As[c4 * 4 + 2][row] = a.z;
            As[c4 * 4 + 3][row] = a.w;
        }
        // Load W tile: 64 rows x 16 cols = 256 float4, 1 per thread
        {
            int n = tid >> 2, c4 = tid & 3;
            float4 w4 = *reinterpret_cast<const float4*>(
                &W[(size_t)(n0 + n) * EE + k0 + c4 * 4]);
            Bs[c4 * 4 + 0][n] = w4.x;
            Bs[c4 * 4 + 1][n] = w4.y;
            Bs[c4 * 4 + 2][n] = w4.z;
            Bs[c4 * 4 + 3][n] = w4.w;
        }
        __syncthreads();

#pragma unroll
        for (int kk = 0; kk < BK; kk++) {
            float4 a0 = *reinterpret_cast<float4*>(&As[kk][ty * 8]);
            float4 a1 = *reinterpret_cast<float4*>(&As[kk][ty * 8 + 4]);
            float4 b0 = *reinterpret_cast<float4*>(&Bs[kk][tx * 4]);
            float ar[8] = {a0.x, a0.y, a0.z, a0.w, a1.x, a1.y, a1.z, a1.w};
            float br[4] = {b0.x, b0.y, b0.z, b0.w};
#pragma unroll
            for (int i = 0; i < 8; i++)
#pragma unroll
                for (int j = 0; j < 4; j++) acc[i][j] += ar[i] * br[j];
        }
        __syncthreads();
    }

    float bv[4] = {0.f, 0.f, 0.f, 0.f};
    if (bias) {
#pragma unroll
        for (int j = 0; j < 4; j++) bv[j] = bias[n0 + tx * 4 + j];
    }
#pragma unroll
    for (int i = 0; i < 8; i++) {
        float4 r;
        r.x = acc[i][0] * scale + bv[0];
        r.y = acc[i][1] * scale + bv[1];
        r.z = acc[i][2] * scale + bv[2];
        r.w = acc[i][3] * scale + bv[3];
        *reinterpret_cast<float4*>(
            &C[(size_t)(m0 + ty * 8 + i) * EE + n0 + tx * 4]) = r;
    }
}

// ---------------------------------------------------------------------------
// Attention: per CTA = (32 query rows) x (one b,h). Full 32x1024 score panel
// in shared memory; two-pass softmax; then PV.
// smem: sS[32][1025] + sQ[32][33] + sKV[64][33] + sInv[32]  ~ 144 KB dynamic
// ---------------------------------------------------------------------------
__global__ __launch_bounds__(256) void attn_kernel(
    const float* __restrict__ bias, const float* __restrict__ mask,
    const float* __restrict__ Qh, const float* __restrict__ Kh,
    const float* __restrict__ Vh, float* __restrict__ O)
{
    extern __shared__ float sm[];
    float* sS   = sm;                        // 32*1025
    float* sQ   = sS + 32 * 1025;            // 32*33
    float* sKV  = sQ + 32 * 33;              // 64*33
    float* sInv = sKV + 64 * 33;             // 32

    const int tid = threadIdx.x;
    const int b = blockIdx.z, h = blockIdx.y;
    const int q0 = blockIdx.x * 32;

    // Load Q tile (32x32) into smem, then each thread caches its q-row in regs
#pragma unroll
    for (int i = 0; i < 4; i++) {
        int idx = tid + 256 * i;
        int qi = idx >> 5, d = idx & 31;
        sQ[qi * 33 + d] = Qh[(size_t)(b * SS + q0 + qi) * EE + h * DD + d];
    }
    __syncthreads();

    const int qi_me = tid >> 3;   // 0..31, thread's fixed query row for QK^T
    const int to    = tid & 7;
    float qreg[32];
#pragma unroll
    for (int d = 0; d < 32; d++) qreg[d] = sQ[qi_me * 33 + d];

    const float* biasRow = bias + (size_t)((b * HH + h) * SS + (q0 + qi_me)) * SS;
    const float* maskRow = mask + (size_t)b * SS;

    // ---- Phase 1: scores = Q·K^T + bias + mask ----
    for (int kt = 0; kt < 16; kt++) {
        const int tbase = kt * 64;
        __syncthreads();   // prior tile's reads complete before overwrite
#pragma unroll
        for (int i = 0; i < 8; i++) {
            int idx = tid + 256 * i;
            int tt = idx >> 5, d = idx & 31;
            sKV[tt * 33 + d] = Kh[(size_t)(b * SS + tbase + tt) * EE + h * DD + d];
        }
        __syncthreads();
#pragma unroll
        for (int j = 0; j < 8; j++) {
            int tt = to + 8 * j;
            float acc = 0.f;
#pragma unroll
            for (int d = 0; d < 32; d++) acc += qreg[d] * sKV[tt * 33 + d];
            int t = tbase + tt;
            sS[qi_me * 1025 + t] = acc + biasRow[t] + maskRow[t];
        }
    }
    __syncthreads();

    // ---- Phase 2: softmax over keys (warp w handles rows 4w..4w+3) ----
    const int lane = tid & 31, w = tid >> 5;
    for (int r = 0; r < 4; r++) {
        int qi = w * 4 + r;
        float* row = sS + qi * 1025;
        float m = -1e30f;
#pragma unroll
        for (int kk = 0; kk < 32; kk++) m = fmaxf(m, row[lane + 32 * kk]);
#pragma unroll
        for (int o = 16; o > 0; o >>= 1) m = fmaxf(m, __shfl_xor_sync(0xffffffffu, m, o));
        float s = 0.f;
#pragma unroll
        for (int kk = 0; kk < 32; kk++) {
            float e = __expf(row[lane + 32 * kk] - m);
            row[lane + 32 * kk] = e;
            s += e;
        }
#pragma unroll
        for (int o = 16; o > 0; o >>= 1) s += __shfl_xor_sync(0xffffffffu, s, o);
        if (lane == 0) sInv[qi] = 1.f / s;
    }
    __syncthreads();

    // ---- Phase 3: O = P·V ---- each thread owns (qi = w+8jj, d = lane)
    const int d = tid & 31;
    float acc[4] = {0.f, 0.f, 0.f, 0.f};
    for (int kt = 0; kt < 16; kt++) {
        const int tbase = kt * 64;
        __syncthreads();
#pragma unroll
        for (int i = 0; i < 8; i++) {
            int idx = tid + 256 * i;
            int tt = idx >> 5, dd = idx & 31;
            sKV[tt * 33 + dd] = Vh[(size_t)(b * SS + tbase + tt) * EE + h * DD + dd];
        }
        __syncthreads();
#pragma unroll 8
        for (int tt = 0; tt < 64; tt++) {
            float v = sKV[tt * 33 + d];
#pragma unroll
            for (int jj = 0; jj < 4; jj++)
                acc[jj] += sS[(w + 8 * jj) * 1025 + tbase + tt] * v;
        }
    }
#pragma unroll
    for (int jj = 0; jj < 4; jj++) {
        int qi = w + 8 * jj;
        O[(size_t)(b * SS + q0 + qi) * EE + h * DD + d] = acc[jj] * sInv[qi];
    }
}

// ---------------------------------------------------------------------------
extern "C" void kernel_launch(void* const* d_in, const int* in_sizes, int n_in,
                              void* d_out, int out_size)
{
    const float* q    = (const float*)d_in[0];
    const float* k    = (const float*)d_in[1];
    const float* v    = (const float*)d_in[2];
    const float* bias = (const float*)d_in[3];
    const float* mask = (const float*)d_in[4];
    const float* Wq   = (const float*)d_in[5];
    const float* Wk   = (const float*)d_in[6];
    const float* Wv   = (const float*)d_in[7];
    const float* Wo   = (const float*)d_in[8];
    const float* bo   = (const float*)d_in[9];
    const float* Wg   = (const float*)d_in[10];
    const float* bg   = (const float*)d_in[11];
    float* out = (float*)d_out;
    (void)in_sizes; (void)n_in; (void)out_size;

    float *Qh, *Kh, *Vh, *G, *O;
    cudaGetSymbolAddress((void**)&Qh, g_Qh);
    cudaGetSymbolAddress((void**)&Kh, g_Kh);
    cudaGetSymbolAddress((void**)&Vh, g_Vh);
    cudaGetSymbolAddress((void**)&G,  g_G);
    cudaGetSymbolAddress((void**)&O,  g_O);

    const dim3 ggrid(EE / 64, (BB * SS) / 128);  // (4, 64)

    // Projections
    sgemm_kernel<<<ggrid, 256>>>(q, Wq, nullptr, nullptr, Qh, NORM_F);
    sgemm_kernel<<<ggrid, 256>>>(k, Wk, nullptr, nullptr, Kh, 1.f);
    sgemm_kernel<<<ggrid, 256>>>(v, Wv, nullptr, nullptr, Vh, 1.f);
    sgemm_kernel<<<ggrid, 256>>>(q, Wg, bg,      nullptr, G,  1.f);

    // Attention
    const size_t smem = (size_t)(32 * 1025 + 32 * 33 + 64 * 33 + 32) * sizeof(float);
    cudaFuncSetAttribute(attn_kernel, cudaFuncAttributeMaxDynamicSharedMemorySize,
                         (int)smem);
    dim3 agrid(SS / 32, HH, BB);   // (32, 8, 8)
    attn_kernel<<<agrid, 256, smem>>>(bias, mask, Qh, Kh, Vh, O);

    // Gated output projection: out = (sigmoid(G) * O) @ Wo^T + bo
    sgemm_kernel<<<ggrid, 256>>>(O, Wo, bo, G, out, 1.f);
}

// round 2
// speedup vs baseline: 2.7148x; 2.7148x over previous
#include <cuda_runtime.h>

// Problem constants
#define BB 8
#define SS 1024
#define EE 256
#define HH 8
#define DD 32
static constexpr float NORM_F = 0.17677669529663687f;  // 1/sqrt(32)

// Scratch (allocation-free): 5 x [B,S,E] fp32 = 40 MB
__device__ float g_Qh[BB * SS * EE];
__device__ float g_Kh[BB * SS * EE];
__device__ float g_Vh[BB * SS * EE];
__device__ float g_G [BB * SS * EE];
__device__ float g_O [BB * SS * EE];

// ---------------------------------------------------------------------------
// Fast exp: FFMA-pipe only (no MUFU). |rel err| < 2e-5 on x in [-87, 0].
// ---------------------------------------------------------------------------
__device__ __forceinline__ float fexp(float x)
{
    float y  = fmaxf(x, -87.0f) * 1.4426950408889634f;  // x*log2(e)
    float rz = y + 12582912.0f;                          // round to nearest int
    int   i  = __float_as_int(rz) - 0x4B400000;          // = round(y)
    float f  = y - (rz - 12582912.0f);                   // f in [-0.5, 0.5]
    float p  = 1.3333558e-3f;                            // 2^f Taylor (deg 5)
    p = fmaf(p, f, 9.6181291e-3f);
    p = fmaf(p, f, 5.5504109e-2f);
    p = fmaf(p, f, 2.4022651e-1f);
    p = fmaf(p, f, 6.9314718e-1f);
    p = fmaf(p, f, 1.0f);
    return __int_as_float(__float_as_int(p) + (i << 23));
}

// ---------------------------------------------------------------------------
// SGEMM body (shared by proj4 and final gemm):
// C[M,256] = scale*(A_eff @ W^T) + bias?, A_eff = A * sigmoid(gate)?
// Tile 128x64x16, 256 threads, 8x4 per-thread microtile.
// ---------------------------------------------------------------------------
__device__ __forceinline__ void sgemm_body(
    const float* __restrict__ A, const float* __restrict__ W,
    const float* __restrict__ bias, const float* __restrict__ gate,
    float* __restrict__ C, float scale, int m0, int n0,
    float (*As)[128], float (*Bs)[64])
{
    const int tid = threadIdx.x;
    const int tx = tid % 16;       // n direction (x4)
    const int ty = tid / 16;       // m direction (x8)

    float acc[8][4];
#pragma unroll
    for (int i = 0; i < 8; i++)
#pragma unroll
        for (int j = 0; j < 4; j++) acc[i][j] = 0.f;

    for (int k0 = 0; k0 < EE; k0 += 16) {
#pragma unroll
        for (int i = 0; i < 2; i++) {
            int idx = tid + 256 * i;
            int row = idx >> 2, c4 = idx & 3;
            size_t goff = (size_t)(m0 + row) * EE + k0 + c4 * 4;
            float4 a = *reinterpret_cast<const float4*>(&A[goff]);
            if (gate) {
                float4 g = *reinterpret_cast<const float4*>(&gate[goff]);
                a.x *= 1.f / (1.f + fexp(-g.x));
                a.y *= 1.f / (1.f + fexp(-g.y));
                a.z *= 1.f / (1.f + fexp(-g.z));
                a.w *= 1.f / (1.f + fexp(-g.w));
            }
            As[c4 * 4 + 0][row] = a.x;
            As[c4 * 4 + 1][row] = a.y;
            As[c4 * 4 + 2][row] = a.z;
            As[c4 * 4 + 3][row] = a.w;
        }
        {
            int n = tid >> 2, c4 = tid & 3;
            float4 w4 = *reinterpret_cast<const float4*>(
                &W[(size_t)(n0 + n) * EE + k0 + c4 * 4]);
            Bs[c4 * 4 + 0][n] = w4.x;
            Bs[c4 * 4 + 1][n] = w4.y;
            Bs[c4 * 4 + 2][n] = w4.z;
            Bs[c4 * 4 + 3][n] = w4.w;
        }
        __syncthreads();
#pragma unroll
        for (int kk = 0; kk < 16; kk++) {
            float4 a0 = *reinterpret_cast<float4*>(&As[kk][ty * 8]);
            float4 a1 = *reinterpret_cast<float4*>(&As[kk][ty * 8 + 4]);
            float4 b0 = *reinterpret_cast<float4*>(&Bs[kk][tx * 4]);
            float ar[8] = {a0.x, a0.y, a0.z, a0.w, a1.x, a1.y, a1.z, a1.w};
            float br[4] = {b0.x, b0.y, b0.z, b0.w};
#pragma unroll
            for (int i = 0; i < 8; i++)
#pragma unroll
                for (int j = 0; j < 4; j++) acc[i][j] += ar[i] * br[j];
        }
        __syncthreads();
    }

    float bv[4] = {0.f, 0.f, 0.f, 0.f};
    if (bias) {
#pragma unroll
        for (int j = 0; j < 4; j++) bv[j] = bias[n0 + tx * 4 + j];
    }
#pragma unroll
    for (int i = 0; i < 8; i++) {
        float4 r;
        r.x = acc[i][0] * scale + bv[0];
        r.y = acc[i][1] * scale + bv[1];
        r.z = acc[i][2] * scale + bv[2];
        r.w = acc[i][3] * scale + bv[3];
        *reinterpret_cast<float4*>(
            &C[(size_t)(m0 + ty * 8 + i) * EE + n0 + tx * 4]) = r;
    }
}

// Merged 4-projection kernel: z selects {Q,K,V,G} projection.
__global__ __launch_bounds__(256) void proj4_kernel(
    const float* __restrict__ q, const float* __restrict__ k,
    const float* __restrict__ v,
    const float* __restrict__ Wq, const float* __restrict__ Wk,
    const float* __restrict__ Wv, const float* __restrict__ Wg,
    const float* __restrict__ bg,
    float* __restrict__ Qh, float* __restrict__ Kh,
    float* __restrict__ Vh, float* __restrict__ G)
{
    __shared__ float As[16][128];
    __shared__ float Bs[16][64];
    const float* A; const float* W; const float* bias = nullptr;
    float* C; float scale = 1.f;
    switch (blockIdx.z) {
        case 0: A = q; W = Wq; C = Qh; scale = NORM_F; break;
        case 1: A = k; W = Wk; C = Kh; break;
        case 2: A = v; W = Wv; C = Vh; break;
        default: A = q; W = Wg; C = G; bias = bg; break;
    }
    sgemm_body(A, W, bias, nullptr, C, scale,
               blockIdx.y * 128, blockIdx.x * 64, As, Bs);
}

// Final gated output projection
__global__ __launch_bounds__(256) void gemm_gate_kernel(
    const float* __restrict__ A, const float* __restrict__ W,
    const float* __restrict__ bias, const float* __restrict__ gate,
    float* __restrict__ C)
{
    __shared__ float As[16][128];
    __shared__ float Bs[16][64];
    sgemm_body(A, W, bias, gate, C, 1.f,
               blockIdx.y * 128, blockIdx.x * 64, As, Bs);
}

// ---------------------------------------------------------------------------
// Attention: per CTA = 32 query rows x (one b,h). Full 32x1024 score panel in
// smem; register-microtiled QK^T (4q x 4t) and PV (8q x 4d, split-K by warp);
// FFMA-only softmax with fused coalesced bias+mask load.
//
// smem (floats): sS[32*1025] | sQt[32*36] | sInv[32] | union{sKt[32*129],
//                sV[128*36], sRed[8*32*36]}  -> 172.8 KB
// ---------------------------------------------------------------------------
#define SM_SS    0
#define SM_QT    (32 * 1025)
#define SM_INV   (SM_QT + 32 * 36)
#define SM_U     (SM_INV + 32)
#define SM_TOTAL (SM_U + 8 * 32 * 36)

__global__ __launch_bounds__(256) void attn_kernel(
    const float* __restrict__ bias, const float* __restrict__ mask,
    const float* __restrict__ Qh, const float* __restrict__ Kh,
    const float* __restrict__ Vh, float* __restrict__ O)
{
    extern __shared__ float sm[];
    float* sS   = sm + SM_SS;    // pitch 1025
    float* sQt  = sm + SM_QT;    // [d][q] pitch 36
    float* sInv = sm + SM_INV;
    float* sU   = sm + SM_U;     // union region

    const int tid  = threadIdx.x;
    const int lane = tid & 31;
    const int w    = tid >> 5;           // warp id 0..7
    const int b = blockIdx.z, h = blockIdx.y;
    const int q0 = blockIdx.x * 32;

    // ---- Load Q tile transposed: sQt[d][q] ----
    {
        int qi = tid >> 3, c = tid & 7;
        float4 qv = *reinterpret_cast<const float4*>(
            &Qh[(size_t)(b * SS + q0 + qi) * EE + h * DD + 4 * c]);
        sQt[(4 * c + 0) * 36 + qi] = qv.x;
        sQt[(4 * c + 1) * 36 + qi] = qv.y;
        sQt[(4 * c + 2) * 36 + qi] = qv.z;
        sQt[(4 * c + 3) * 36 + qi] = qv.w;
    }

    // ---- Phase 1: scores = Q.K^T  (4q x 4t per thread, Tk=128) ----
    float* sKt = sU;   // [d][t] pitch 129
    const int qg = w;              // q group: rows 4w..4w+3
    const int tg = lane;
    for (int kt = 0; kt < 8; kt++) {
        const int tbase = kt * 128;
        __syncthreads();
#pragma unroll
        for (int i = 0; i < 4; i++) {
            int idx = tid + 256 * i;
            int t = idx >> 3, c = idx & 7;
            float4 kv = *reinterpret_cast<const float4*>(
                &Kh[(size_t)(b * SS + tbase + t) * EE + h * DD + 4 * c]);
            sKt[(4 * c + 0) * 129 + t] = kv.x;
            sKt[(4 * c + 1) * 129 + t] = kv.y;
            sKt[(4 * c + 2) * 129 + t] = kv.z;
            sKt[(4 * c + 3) * 129 + t] = kv.w;
        }
        __syncthreads();

        float acc[4][4];
#pragma unroll
        for (int i = 0; i < 4; i++)
#pragma unroll
            for (int j = 0; j < 4; j++) acc[i][j] = 0.f;

#pragma unroll
        for (int d = 0; d < 32; d++) {
            float4 qv = *reinterpret_cast<float4*>(&sQt[d * 36 + qg * 4]);
            float k0 = sKt[d * 129 + tg];
            float k1 = sKt[d * 129 + tg + 32];
            float k2 = sKt[d * 129 + tg + 64];
            float k3 = sKt[d * 129 + tg + 96];
            acc[0][0] += qv.x * k0; acc[0][1] += qv.x * k1;
            acc[0][2] += qv.x * k2; acc[0][3] += qv.x * k3;
            acc[1][0] += qv.y * k0; acc[1][1] += qv.y * k1;
            acc[1][2] += qv.y * k2; acc[1][3] += qv.y * k3;
            acc[2][0] += qv.z * k0; acc[2][1] += qv.z * k1;
            acc[2][2] += qv.z * k2; acc[2][3] += qv.z * k3;
            acc[3][0] += qv.w * k0; acc[3][1] += qv.w * k1;
            acc[3][2] += qv.w * k2; acc[3][3] += qv.w * k3;
        }
#pragma unroll
        for (int i = 0; i < 4; i++)
#pragma unroll
            for (int j = 0; j < 4; j++)
                sS[(qg * 4 + i) * 1025 + tbase + tg + 32 * j] = acc[i][j];
    }
    __syncthreads();

    // ---- Phase 2: softmax (warp w owns rows 4w..4w+3); fused bias+mask ----
    const float* maskRow = mask + (size_t)b * SS;
    for (int r = 0; r < 4; r++) {
        const int qi = w * 4 + r;
        const float* bRow =
            bias + (size_t)((b * HH + h) * SS + (q0 + qi)) * SS;
        float* row = sS + qi * 1025;
        float m = -1e30f;
#pragma unroll
        for (int seg = 0; seg < 8; seg++) {
            int t = seg * 128 + lane * 4;
            float4 bv = *reinterpret_cast<const float4*>(&bRow[t]);
            float4 mv = *reinterpret_cast<const float4*>(&maskRow[t]);
            float s0 = row[t + 0] + bv.x + mv.x;
            float s1 = row[t + 1] + bv.y + mv.y;
            float s2 = row[t + 2] + bv.z + mv.z;
            float s3 = row[t + 3] + bv.w + mv.w;
            row[t + 0] = s0; row[t + 1] = s1; row[t + 2] = s2; row[t + 3] = s3;
            m = fmaxf(m, fmaxf(fmaxf(s0, s1), fmaxf(s2, s3)));
        }
#pragma unroll
        for (int o = 16; o > 0; o >>= 1)
            m = fmaxf(m, __shfl_xor_sync(0xffffffffu, m, o));
        float sum = 0.f;
#pragma unroll
        for (int seg = 0; seg < 8; seg++) {
            int t = seg * 128 + lane * 4;
            float e0 = fexp(row[t + 0] - m);
            float e1 = fexp(row[t + 1] - m);
            float e2 = fexp(row[t + 2] - m);
            float e3 = fexp(row[t + 3] - m);
            row[t + 0] = e0; row[t + 1] = e1; row[t + 2] = e2; row[t + 3] = e3;
            sum += (e0 + e1) + (e2 + e3);
        }
#pragma unroll
        for (int o = 16; o > 0; o >>= 1)
            sum += __shfl_xor_sync(0xffffffffu, sum, o);
        if (lane == 0) sInv[qi] = 1.f / sum;
    }
    __syncthreads();

    // ---- Phase 3: O = P.V  (lane: 8q x 4d; warp w covers 16 t per tile) ----
    float* sV = sU;                 // [t][d] pitch 36
    const int qb = (lane >> 3) * 8; // lane's q base
    const int d0 = (lane & 7) * 4;  // lane's d base
    float acc[8][4];
#pragma unroll
    for (int i = 0; i < 8; i++)
#pragma unroll
        for (int j = 0; j < 4; j++) acc[i][j] = 0.f;

    for (int kt = 0; kt < 8; kt++) {
        const int tbase = kt * 128;
        __syncthreads();
#pragma unroll
        for (int i = 0; i < 4; i++) {
            int idx = tid + 256 * i;
            int t = idx >> 3, c = idx & 7;
            float4 vv = *reinterpret_cast<const float4*>(
                &Vh[(size_t)(b * SS + tbase + t) * EE + h * DD + 4 * c]);
            *reinterpret_cast<float4*>(&sV[t * 36 + 4 * c]) = vv;
        }
        __syncthreads();
#pragma unroll
        for (int s = 0; s < 16; s++) {
            const int tt = w * 16 + s;
            const int t = tbase + tt;
            float4 vv = *reinterpret_cast<float4*>(&sV[tt * 36 + d0]);
#pragma unroll
            for (int i = 0; i < 8; i++) {
                float p = sS[(qb + i) * 1025 + t];
                acc[i][0] += p * vv.x;
                acc[i][1] += p * vv.y;
                acc[i][2] += p * vv.z;
                acc[i][3] += p * vv.w;
            }
        }
    }

    // ---- Cross-warp reduction of the split-K partials ----
    float* sRed = sU;  // [warp][q][36]
    __syncthreads();
#pragma unroll
    for (int i = 0; i < 8; i++) {
        *reinterpret_cast<float4*>(&sRed[(w * 32 + qb + i) * 36 + d0]) =
            make_float4(acc[i][0], acc[i][1], acc[i][2], acc[i][3]);
    }
    __syncthreads();
    {
        const int q = tid >> 3, dd = (tid & 7) * 4;
        float4 o = make_float4(0.f, 0.f, 0.f, 0.f);
#pragma unroll
        for (int w2 = 0; w2 < 8; w2++) {
            float4 p = *reinterpret_cast<float4*>(&sRed[(w2 * 32 + q) * 36 + dd]);
            o.x += p.x; o.y += p.y; o.z += p.z; o.w += p.w;
        }
        float inv = sInv[q];
        o.x *= inv; o.y *= inv; o.z *= inv; o.w *= inv;
        *reinterpret_cast<float4*>(
            &O[(size_t)(b * SS + q0 + q) * EE + h * DD + dd]) = o;
    }
}

// ---------------------------------------------------------------------------
extern "C" void kernel_launch(void* const* d_in, const int* in_sizes, int n_in,
                              void* d_out, int out_size)
{
    const float* q    = (const float*)d_in[0];
    const float* k    = (const float*)d_in[1];
    const float* v    = (const float*)d_in[2];
    const float* bias = (const float*)d_in[3];
    const float* mask = (const float*)d_in[4];
    const float* Wq   = (const float*)d_in[5];
    const float* Wk   = (const float*)d_in[6];
    const float* Wv   = (const float*)d_in[7];
    const float* Wo   = (const float*)d_in[8];
    const float* bo   = (const float*)d_in[9];
    const float* Wg   = (const float*)d_in[10];
    const float* bg   = (const float*)d_in[11];
    float* out = (float*)d_out;
    (void)in_sizes; (void)n_in; (void)out_size;

    float *Qh, *Kh, *Vh, *G, *O;
    cudaGetSymbolAddress((void**)&Qh, g_Qh);
    cudaGetSymbolAddress((void**)&Kh, g_Kh);
    cudaGetSymbolAddress((void**)&Vh, g_Vh);
    cudaGetSymbolAddress((void**)&G,  g_G);
    cudaGetSymbolAddress((void**)&O,  g_O);

    // 4 projections in one launch (z-indexed)
    dim3 pgrid(EE / 64, (BB * SS) / 128, 4);   // (4, 64, 4) = 1024 CTAs
    proj4_kernel<<<pgrid, 256>>>(q, k, v, Wq, Wk, Wv, Wg, bg, Qh, Kh, Vh, G);

    // Attention
    const size_t smem = (size_t)SM_TOTAL * sizeof(float);
    cudaFuncSetAttribute(attn_kernel, cudaFuncAttributeMaxDynamicSharedMemorySize,
                         (int)smem);
    dim3 agrid(SS / 32, HH, BB);               // (32, 8, 8)
    attn_kernel<<<agrid, 256, smem>>>(bias, mask, Qh, Kh, Vh, O);

    // Gated output projection: out = (sigmoid(G) * O) @ Wo^T + bo
    dim3 ggrid(EE / 64, (BB * SS) / 128);
    gemm_gate_kernel<<<ggrid, 256>>>(O, Wo, bo, G, out);
}

// round 5
// speedup vs baseline: 4.0353x; 1.4864x over previous
#include <cuda_runtime.h>
#include <cstdint>

// Problem constants
#define BB 8
#define SS 1024
#define EE 256
#define HH 8
#define DD 32
static constexpr float NORM_F = 0.17677669529663687f;  // 1/sqrt(32)

// Scratch (allocation-free): 5 x [B,S,E] fp32 = 40 MB
__device__ float g_Qh[BB * SS * EE];
__device__ float g_Kh[BB * SS * EE];
__device__ float g_Vh[BB * SS * EE];
__device__ float g_G [BB * SS * EE];
__device__ float g_O [BB * SS * EE];

// ---------------------------------------------------------------------------
// Helpers
// ---------------------------------------------------------------------------
__device__ __forceinline__ float fexp(float x)
{
    float y  = fmaxf(x, -87.0f) * 1.4426950408889634f;
    float rz = y + 12582912.0f;
    int   i  = __float_as_int(rz) - 0x4B400000;
    float f  = y - (rz - 12582912.0f);
    float p  = 1.3333558e-3f;
    p = fmaf(p, f, 9.6181291e-3f);
    p = fmaf(p, f, 5.5504109e-2f);
    p = fmaf(p, f, 2.4022651e-1f);
    p = fmaf(p, f, 6.9314718e-1f);
    p = fmaf(p, f, 1.0f);
    return __int_as_float(__float_as_int(p) + (i << 23));
}

__device__ __forceinline__ uint32_t f2t(float x)
{
    uint32_t r;
    asm("cvt.rna.tf32.f32 %0, %1;" : "=r"(r) : "f"(x));
    return r;
}
__device__ __forceinline__ float f2tf(float x) { return __uint_as_float(f2t(x)); }

// mma.sync m16n8k8 tf32: D += A*B (fp32 accum)
__device__ __forceinline__ void mma8(float* c, const uint32_t* a, const uint32_t* b)
{
    asm volatile(
        "mma.sync.aligned.m16n8k8.row.col.f32.tf32.tf32.f32 "
        "{%0,%1,%2,%3}, {%4,%5,%6,%7}, {%8,%9}, {%0,%1,%2,%3};"
        : "+f"(c[0]), "+f"(c[1]), "+f"(c[2]), "+f"(c[3])
        : "r"(a[0]), "r"(a[1]), "r"(a[2]), "r"(a[3]), "r"(b[0]), "r"(b[1]));
}

// ---------------------------------------------------------------------------
// tf32 tensor-core GEMM body: C[M,256] = scale*(A_eff @ W^T) + bias?
// A_eff = A * sigmoid(gate)? ; CTA tile 128x64, 8 warps (2x4), warp 64x16.
// ---------------------------------------------------------------------------
template <bool GATE, bool OUTCVT>
__device__ __forceinline__ void mgemm_body(
    const float* __restrict__ A, const float* __restrict__ W,
    const float* __restrict__ bias, const float* __restrict__ gate,
    float* __restrict__ C, float scale, int m0, int n0,
    float* sA /*128*36*/, float* sW /*32*68*/)
{
    const int tid = threadIdx.x, lane = tid & 31, w = tid >> 5;
    const int wm = w >> 2, wn = w & 3;
    const int g = lane >> 2, tg = lane & 3;

    float acc[4][2][4];
#pragma unroll
    for (int mi = 0; mi < 4; mi++)
#pragma unroll
        for (int nj = 0; nj < 2; nj++)
#pragma unroll
            for (int r = 0; r < 4; r++) acc[mi][nj][r] = 0.f;

    for (int k0 = 0; k0 < EE; k0 += 32) {
#pragma unroll
        for (int i = 0; i < 4; i++) {
            int idx = tid + 256 * i;           // 0..1023
            int row = idx >> 3, c = idx & 7;
            size_t go = (size_t)(m0 + row) * EE + k0 + 4 * c;
            float4 a = *reinterpret_cast<const float4*>(&A[go]);
            if (GATE) {
                float4 gg = *reinterpret_cast<const float4*>(&gate[go]);
                a.x *= 1.f / (1.f + fexp(-gg.x));
                a.y *= 1.f / (1.f + fexp(-gg.y));
                a.z *= 1.f / (1.f + fexp(-gg.z));
                a.w *= 1.f / (1.f + fexp(-gg.w));
            }
            sA[row * 36 + 4 * c + 0] = f2tf(a.x);
            sA[row * 36 + 4 * c + 1] = f2tf(a.y);
            sA[row * 36 + 4 * c + 2] = f2tf(a.z);
            sA[row * 36 + 4 * c + 3] = f2tf(a.w);
        }
#pragma unroll
        for (int i = 0; i < 2; i++) {
            int idx = tid + 256 * i;           // 0..511
            int n = idx >> 3, c = idx & 7;
            float4 ww = *reinterpret_cast<const float4*>(
                &W[(size_t)(n0 + n) * EE + k0 + 4 * c]);
            sW[(4 * c + 0) * 68 + n] = f2tf(ww.x);
            sW[(4 * c + 1) * 68 + n] = f2tf(ww.y);
            sW[(4 * c + 2) * 68 + n] = f2tf(ww.z);
            sW[(4 * c + 3) * 68 + n] = f2tf(ww.w);
        }
        __syncthreads();

#pragma unroll
        for (int kk = 0; kk < 4; kk++) {
            uint32_t af[4][4];
#pragma unroll
            for (int mi = 0; mi < 4; mi++) {
                int r = wm * 64 + mi * 16 + g;
                int cc = kk * 8 + tg;
                af[mi][0] = __float_as_uint(sA[r * 36 + cc]);
                af[mi][1] = __float_as_uint(sA[(r + 8) * 36 + cc]);
                af[mi][2] = __float_as_uint(sA[r * 36 + cc + 4]);
                af[mi][3] = __float_as_uint(sA[(r + 8) * 36 + cc + 4]);
            }
            uint32_t bf[2][2];
#pragma unroll
            for (int nj = 0; nj < 2; nj++) {
                int n = wn * 16 + nj * 8 + g;
                int r = kk * 8 + tg;
                bf[nj][0] = __float_as_uint(sW[r * 68 + n]);
                bf[nj][1] = __float_as_uint(sW[(r + 4) * 68 + n]);
            }
#pragma unroll
            for (int mi = 0; mi < 4; mi++)
#pragma unroll
                for (int nj = 0; nj < 2; nj++) mma8(acc[mi][nj], af[mi], bf[nj]);
        }
        __syncthreads();
    }

#pragma unroll
    for (int mi = 0; mi < 4; mi++)
#pragma unroll
        for (int nj = 0; nj < 2; nj++) {
            int r0 = m0 + wm * 64 + mi * 16 + g;
            int cn = n0 + wn * 16 + nj * 8 + 2 * tg;
            float b0 = 0.f, b1 = 0.f;
            if (bias) { b0 = bias[cn]; b1 = bias[cn + 1]; }
            float v0 = acc[mi][nj][0] * scale + b0;
            float v1 = acc[mi][nj][1] * scale + b1;
            float v2 = acc[mi][nj][2] * scale + b0;
            float v3 = acc[mi][nj][3] * scale + b1;
            if (OUTCVT) { v0 = f2tf(v0); v1 = f2tf(v1); v2 = f2tf(v2); v3 = f2tf(v3); }
            *reinterpret_cast<float2*>(&C[(size_t)r0 * EE + cn]) =
                make_float2(v0, v1);
            *reinterpret_cast<float2*>(&C[(size_t)(r0 + 8) * EE + cn]) =
                make_float2(v2, v3);
        }
}

// Merged 4-projection kernel: z selects {Q,K,V,G}.
__global__ __launch_bounds__(256) void proj4_kernel(
    const float* __restrict__ q, const float* __restrict__ k,
    const float* __restrict__ v,
    const float* __restrict__ Wq, const float* __restrict__ Wk,
    const float* __restrict__ Wv, const float* __restrict__ Wg,
    const float* __restrict__ bg,
    float* __restrict__ Qh, float* __restrict__ Kh,
    float* __restrict__ Vh, float* __restrict__ G)
{
    __shared__ float sA[128 * 36];
    __shared__ float sW[32 * 68];
    const int m0 = blockIdx.y * 128, n0 = blockIdx.x * 64;
    switch (blockIdx.z) {
        case 0: mgemm_body<false, true >(q, Wq, nullptr, nullptr, Qh, NORM_F, m0, n0, sA, sW); break;
        case 1: mgemm_body<false, true >(k, Wk, nullptr, nullptr, Kh, 1.f,    m0, n0, sA, sW); break;
        case 2: mgemm_body<false, true >(v, Wv, nullptr, nullptr, Vh, 1.f,    m0, n0, sA, sW); break;
        default: mgemm_body<false, false>(q, Wg, bg,     nullptr, G,  1.f,    m0, n0, sA, sW); break;
    }
}

__global__ __launch_bounds__(256) void gemm_gate_kernel(
    const float* __restrict__ A, const float* __restrict__ W,
    const float* __restrict__ bias, const float* __restrict__ gate,
    float* __restrict__ C)
{
    __shared__ float sA[128 * 36];
    __shared__ float sW[32 * 68];
    mgemm_body<true, false>(A, W, bias, gate, C, 1.f,
                            blockIdx.y * 128, blockIdx.x * 64, sA, sW);
}

// ---------------------------------------------------------------------------
// Attention: CTA = 32 queries x (b,h). tf32 mma for QK^T and PV.
// smem: sS[32*1032] | sInv[32] | sU = max(K tile 128*36, V tile 128*40,
//       reduction 8*32*36) = 9216 floats.  Total 169 KB.
// ---------------------------------------------------------------------------
#define SM_SS    0
#define SM_INV   (32 * 1032)
#define SM_U     (SM_INV + 32)
#define SM_TOTAL (SM_U + 8 * 32 * 36)

__global__ __launch_bounds__(256) void attn_kernel(
    const float* __restrict__ bias, const float* __restrict__ mask,
    const float* __restrict__ Qh, const float* __restrict__ Kh,
    const float* __restrict__ Vh, float* __restrict__ O)
{
    extern __shared__ float sm[];
    float* sS   = sm + SM_SS;    // pitch 1032
    float* sInv = sm + SM_INV;
    float* sU   = sm + SM_U;

    const int tid  = threadIdx.x;
    const int lane = tid & 31;
    const int w    = tid >> 5;
    const int g    = lane >> 2, tg = lane & 3;
    const int b = blockIdx.z, h = blockIdx.y;
    const int q0 = blockIdx.x * 32;

    // ---- Q fragments in registers (Qh is pre-rounded tf32) ----
    uint32_t qa[2][4][4];
    {
        const float* Qb = Qh + (size_t)(b * SS + q0) * EE + h * DD;
#pragma unroll
        for (int mi = 0; mi < 2; mi++)
#pragma unroll
            for (int kk = 0; kk < 4; kk++) {
                int r = mi * 16 + g, d = kk * 8 + tg;
                qa[mi][kk][0] = __float_as_uint(Qb[(size_t)r * EE + d]);
                qa[mi][kk][1] = __float_as_uint(Qb[(size_t)(r + 8) * EE + d]);
                qa[mi][kk][2] = __float_as_uint(Qb[(size_t)r * EE + d + 4]);
                qa[mi][kk][3] = __float_as_uint(Qb[(size_t)(r + 8) * EE + d + 4]);
            }
    }

    // ---- Phase 1: scores = Q.K^T via mma; warp w covers t in [16w,16w+16) ----
    float* sK = sU;   // [t=128][d=32] pitch 36
    for (int kt = 0; kt < 8; kt++) {
        const int tbase = kt * 128;
        __syncthreads();
#pragma unroll
        for (int i = 0; i < 4; i++) {
            int idx = tid + 256 * i;
            int t = idx >> 3, c = idx & 7;
            *reinterpret_cast<float4*>(&sK[t * 36 + 4 * c]) =
                *reinterpret_cast<const float4*>(
                    &Kh[(size_t)(b * SS + tbase + t) * EE + h * DD + 4 * c]);
        }
        __syncthreads();

        float acc[2][2][4];
#pragma unroll
        for (int mi = 0; mi < 2; mi++)
#pragma unroll
            for (int j = 0; j < 2; j++)
#pragma unroll
                for (int r = 0; r < 4; r++) acc[mi][j][r] = 0.f;

#pragma unroll
        for (int kk = 0; kk < 4; kk++) {
            uint32_t bf[2][2];
#pragma unroll
            for (int j = 0; j < 2; j++) {
                int t = 16 * w + 8 * j + g;
                int d = kk * 8 + tg;
                bf[j][0] = __float_as_uint(sK[t * 36 + d]);
                bf[j][1] = __float_as_uint(sK[t * 36 + d + 4]);
            }
#pragma unroll
            for (int mi = 0; mi < 2; mi++)
#pragma unroll
                for (int j = 0; j < 2; j++) mma8(acc[mi][j], qa[mi][kk], bf[j]);
        }
#pragma unroll
        for (int mi = 0; mi < 2; mi++)
#pragma unroll
            for (int j = 0; j < 2; j++) {
                int qq = mi * 16 + g;
                int t = tbase + 16 * w + 8 * j + 2 * tg;
                *reinterpret_cast<float2*>(&sS[qq * 1032 + t]) =
                    make_float2(acc[mi][j][0], acc[mi][j][1]);
                *reinterpret_cast<float2*>(&sS[(qq + 8) * 1032 + t]) =
                    make_float2(acc[mi][j][2], acc[mi][j][3]);
            }
    }
    __syncthreads();

    // ---- Phase 2: softmax rows (warp w owns q rows 4w..4w+3) ----
    const float* maskRow = mask + (size_t)b * SS;
    for (int r = 0; r < 4; r++) {
        const int qi = w * 4 + r;
        const float* bRow = bias + (size_t)((b * HH + h) * SS + (q0 + qi)) * SS;
        float* row = sS + qi * 1032;
        float m = -1e30f;
#pragma unroll
        for (int seg = 0; seg < 8; seg++) {
            int t = seg * 128 + lane * 4;
            float4 sv = *reinterpret_cast<float4*>(&row[t]);
            float4 bv = *reinterpret_cast<const float4*>(&bRow[t]);
            float4 mv = *reinterpret_cast<const float4*>(&maskRow[t]);
            sv.x += bv.x + mv.x; sv.y += bv.y + mv.y;
            sv.z += bv.z + mv.z; sv.w += bv.w + mv.w;
            *reinterpret_cast<float4*>(&row[t]) = sv;
            m = fmaxf(m, fmaxf(fmaxf(sv.x, sv.y), fmaxf(sv.z, sv.w)));
        }
#pragma unroll
        for (int o = 16; o > 0; o >>= 1)
            m = fmaxf(m, __shfl_xor_sync(0xffffffffu, m, o));
        float sum = 0.f;
#pragma unroll
        for (int seg = 0; seg < 8; seg++) {
            int t = seg * 128 + lane * 4;
            float4 sv = *reinterpret_cast<float4*>(&row[t]);
            sv.x = fexp(sv.x - m); sv.y = fexp(sv.y - m);
            sv.z = fexp(sv.z - m); sv.w = fexp(sv.w - m);
            *reinterpret_cast<float4*>(&row[t]) = sv;
            sum += (sv.x + sv.y) + (sv.z + sv.w);
        }
#pragma unroll
        for (int o = 16; o > 0; o >>= 1)
            sum += __shfl_xor_sync(0xffffffffu, sum, o);
        if (lane == 0) sInv[qi] = 1.f / sum;
    }
    __syncthreads();

    // ---- Phase 3: O = P.V via mma; split-K by warp (each warp 16 t/tile) ----
    float* sV = sU;   // [t=128][d=32] pitch 40
    float pacc[2][4][4];
#pragma unroll
    for (int mi = 0; mi < 2; mi++)
#pragma unroll
        for (int nj = 0; nj < 4; nj++)
#pragma unroll
            for (int r = 0; r < 4; r++) pacc[mi][nj][r] = 0.f;

    for (int kt = 0; kt < 8; kt++) {
        const int tbase = kt * 128;
        __syncthreads();
#pragma unroll
        for (int i = 0; i < 4; i++) {
            int idx = tid + 256 * i;
            int t = idx >> 3, c = idx & 7;
            *reinterpret_cast<float4*>(&sV[t * 40 + 4 * c]) =
                *reinterpret_cast<const float4*>(
                    &Vh[(size_t)(b * SS + tbase + t) * EE + h * DD + 4 * c]);
        }
        __syncthreads();
#pragma unroll
        for (int kk2 = 0; kk2 < 2; kk2++) {
            const int t0 = 16 * w + 8 * kk2;
            uint32_t af[2][4];
#pragma unroll
            for (int mi = 0; mi < 2; mi++) {
                int qq = mi * 16 + g;
                af[mi][0] = f2t(sS[qq * 1032 + tbase + t0 + tg]);
                af[mi][1] = f2t(sS[(qq + 8) * 1032 + tbase + t0 + tg]);
                af[mi][2] = f2t(sS[qq * 1032 + tbase + t0 + tg + 4]);
                af[mi][3] = f2t(sS[(qq + 8) * 1032 + tbase + t0 + tg + 4]);
            }
            uint32_t bf[4][2];
#pragma unroll
            for (int nj = 0; nj < 4; nj++) {
                int d = nj * 8 + g;
                bf[nj][0] = __float_as_uint(sV[(t0 + tg) * 40 + d]);
                bf[nj][1] = __float_as_uint(sV[(t0 + tg + 4) * 40 + d]);
            }
#pragma unroll
            for (int mi = 0; mi < 2; mi++)
#pragma unroll
                for (int nj = 0; nj < 4; nj++) mma8(pacc[mi][nj], af[mi], bf[nj]);
        }
    }

    // ---- Cross-warp split-K reduction ----
    float* sRed = sU;   // [w][q][36]
    __syncthreads();
#pragma unroll
    for (int mi = 0; mi < 2; mi++)
#pragma unroll
        for (int nj = 0; nj < 4; nj++) {
            int qq = mi * 16 + g;
            int d = nj * 8 + 2 * tg;
            *reinterpret_cast<float2*>(&sRed[(w * 32 + qq) * 36 + d]) =
                make_float2(pacc[mi][nj][0], pacc[mi][nj][1]);
            *reinterpret_cast<float2*>(&sRed[(w * 32 + qq + 8) * 36 + d]) =
                make_float2(pacc[mi][nj][2], pacc[mi][nj][3]);
        }
    __syncthreads();
    {
        const int qq = tid >> 3, d0 = (tid & 7) * 4;
        float4 o = make_float4(0.f, 0.f, 0.f, 0.f);
#pragma unroll
        for (int w2 = 0; w2 < 8; w2++) {
            float4 p = *reinterpret_cast<float4*>(&sRed[(w2 * 32 + qq) * 36 + d0]);
            o.x += p.x; o.y += p.y; o.z += p.z; o.w += p.w;
        }
        float inv = sInv[qq];
        o.x *= inv; o.y *= inv; o.z *= inv; o.w *= inv;
        *reinterpret_cast<float4*>(
            &O[(size_t)(b * SS + q0 + qq) * EE + h * DD + d0]) = o;
    }
}

// ---------------------------------------------------------------------------
extern "C" void kernel_launch(void* const* d_in, const int* in_sizes, int n_in,
                              void* d_out, int out_size)
{
    const float* q    = (const float*)d_in[0];
    const float* k    = (const float*)d_in[1];
    const float* v    = (const float*)d_in[2];
    const float* bias = (const float*)d_in[3];
    const float* mask = (const float*)d_in[4];
    const float* Wq   = (const float*)d_in[5];
    const float* Wk   = (const float*)d_in[6];
    const float* Wv   = (const float*)d_in[7];
    const float* Wo   = (const float*)d_in[8];
    const float* bo   = (const float*)d_in[9];
    const float* Wg   = (const float*)d_in[10];
    const float* bg   = (const float*)d_in[11];
    float* out = (float*)d_out;
    (void)in_sizes; (void)n_in; (void)out_size;

    float *Qh, *Kh, *Vh, *G, *O;
    cudaGetSymbolAddress((void**)&Qh, g_Qh);
    cudaGetSymbolAddress((void**)&Kh, g_Kh);
    cudaGetSymbolAddress((void**)&Vh, g_Vh);
    cudaGetSymbolAddress((void**)&G,  g_G);
    cudaGetSymbolAddress((void**)&O,  g_O);

    dim3 pgrid(EE / 64, (BB * SS) / 128, 4);
    proj4_kernel<<<pgrid, 256>>>(q, k, v, Wq, Wk, Wv, Wg, bg, Qh, Kh, Vh, G);

    const size_t smem = (size_t)SM_TOTAL * sizeof(float);
    cudaFuncSetAttribute(attn_kernel, cudaFuncAttributeMaxDynamicSharedMemorySize,
                         (int)smem);
    dim3 agrid(SS / 32, HH, BB);
    attn_kernel<<<agrid, 256, smem>>>(bias, mask, Qh, Kh, Vh, O);

    dim3 ggrid(EE / 64, (BB * SS) / 128);
    gemm_gate_kernel<<<ggrid, 256>>>(O, Wo, bo, G, out);
}